// round 1
// baseline (speedup 1.0000x reference)
#include <cuda_runtime.h>
#include <math.h>

#define B_     64
#define A_     512
#define DIM_   256
#define M_     (B_*A_)     // 32768
#define HEADS_ 8
#define DH_    32
#define LAYERS_ 6
#define FF_    2048
#define T_     2016
#define ACT_   6

// ---------------- scratch (static device globals; no allocation) ----------------
__device__ float g_x   [(size_t)M_*DIM_];
__device__ float g_qkv [(size_t)M_*3*DIM_];
__device__ float g_attn[(size_t)M_*DIM_];
__device__ float g_tmp [(size_t)M_*DIM_];
__device__ float g_ff  [(size_t)M_*FF_];
__device__ float g_h1v [B_*DIM_];
__device__ float g_feat[(size_t)T_*5*DIM_];
__device__ float g_o1  [(size_t)T_*DIM_];
__device__ float g_o2  [T_*ACT_];
__device__ int   g_off [B_+1];

__device__ __forceinline__ float sigmoidf_(float x) { return 1.0f / (1.0f + expf(-x)); }

// ---------------- lin0: x = relu(data @ W^T + b), data (M,3) ----------------
__global__ void lin0_kernel(const float* __restrict__ data,
                            const float* __restrict__ w,   // (256,3)
                            const float* __restrict__ b,
                            float* __restrict__ x)
{
    int idx = blockIdx.x * blockDim.x + threadIdx.x;   // M*256 threads
    if (idx >= M_*DIM_) return;
    int m = idx >> 8;
    int n = idx & 255;
    float d0 = data[m*3+0], d1 = data[m*3+1], d2 = data[m*3+2];
    float v = d0*w[n*3+0] + d1*w[n*3+1] + d2*w[n*3+2] + b[n];
    x[idx] = fmaxf(v, 0.0f);
}

// ---------------- generic SGEMM, C[m,n] = act(sum_k A[m,k]*B[n,k] + bias[n]) ----------------
// A: (M,K) row-major; B: (N,K) row-major (i.e. C = A @ B^T). K % 16 == 0.
template<int BIAS, int RELU>
__global__ __launch_bounds__(256)
void sgemm_nt(const float* __restrict__ A, const float* __restrict__ Bm,
              const float* __restrict__ bias, float* __restrict__ C,
              int M, int N, int K)
{
    __shared__ float As[16][64];
    __shared__ float Bs[16][64];
    const int tid = threadIdx.x;
    const int bm = blockIdx.y * 64;
    const int bn = blockIdx.x * 64;
    const int ty = tid >> 4, tx = tid & 15;
    const int lr = tid >> 2;            // 0..63
    const int lk = (tid & 3) << 2;      // 0,4,8,12
    float acc[4][4] = {};

    for (int k0 = 0; k0 < K; k0 += 16) {
        float4 av = make_float4(0.f,0.f,0.f,0.f);
        float4 bv = make_float4(0.f,0.f,0.f,0.f);
        int ar = bm + lr;
        if (ar < M) av = *reinterpret_cast<const float4*>(A  + (size_t)ar*K + k0 + lk);
        int br = bn + lr;
        if (br < N) bv = *reinterpret_cast<const float4*>(Bm + (size_t)br*K + k0 + lk);
        As[lk+0][lr]=av.x; As[lk+1][lr]=av.y; As[lk+2][lr]=av.z; As[lk+3][lr]=av.w;
        Bs[lk+0][lr]=bv.x; Bs[lk+1][lr]=bv.y; Bs[lk+2][lr]=bv.z; Bs[lk+3][lr]=bv.w;
        __syncthreads();
        #pragma unroll
        for (int k = 0; k < 16; k++) {
            float4 a4 = *reinterpret_cast<float4*>(&As[k][ty*4]);
            float4 b4 = *reinterpret_cast<float4*>(&Bs[k][tx*4]);
            float a[4] = {a4.x, a4.y, a4.z, a4.w};
            float bb[4] = {b4.x, b4.y, b4.z, b4.w};
            #pragma unroll
            for (int i = 0; i < 4; i++)
                #pragma unroll
                for (int j = 0; j < 4; j++)
                    acc[i][j] += a[i]*bb[j];
        }
        __syncthreads();
    }

    #pragma unroll
    for (int i = 0; i < 4; i++) {
        int m = bm + ty*4 + i;
        if (m >= M) continue;
        #pragma unroll
        for (int j = 0; j < 4; j++) {
            int n = bn + tx*4 + j;
            if (n >= N) continue;
            float v = acc[i][j];
            if (BIAS) v += bias[n];
            if (RELU) v = fmaxf(v, 0.0f);
            C[(size_t)m*N + n] = v;
        }
    }
}

// ---------------- attention over the batch axis: one block per (atom n, head h) ----------------
__global__ __launch_bounds__(128)
void attn_kernel(const float* __restrict__ qkv, float* __restrict__ attn_out)
{
    int nh = blockIdx.x;
    int n = nh >> 3;
    int h = nh & 7;
    __shared__ float q[64][32], k[64][32], v[64][32];
    __shared__ float sc[64][65];
    int tid = threadIdx.x;

    for (int i = tid; i < 64*32; i += 128) {
        int s = i >> 5, d = i & 31;
        size_t base = ((size_t)(s*A_ + n))*768 + h*32 + d;
        q[s][d] = qkv[base];
        k[s][d] = qkv[base + 256];
        v[s][d] = qkv[base + 512];
    }
    __syncthreads();

    const float scale = 0.17677669529663687f;  // 1/sqrt(32)
    for (int i = tid; i < 64*64; i += 128) {
        int s = i >> 6, t = i & 63;
        float acc = 0.f;
        #pragma unroll 8
        for (int d = 0; d < 32; d++) acc += q[s][d]*k[t][d];
        sc[s][t] = acc * scale;
    }
    __syncthreads();

    if (tid < 64) {
        float mx = -1e30f;
        for (int t = 0; t < 64; t++) mx = fmaxf(mx, sc[tid][t]);
        float sum = 0.f;
        for (int t = 0; t < 64; t++) { float e = expf(sc[tid][t]-mx); sc[tid][t]=e; sum+=e; }
        float inv = 1.0f / sum;
        for (int t = 0; t < 64; t++) sc[tid][t] *= inv;
    }
    __syncthreads();

    for (int i = tid; i < 64*32; i += 128) {
        int s = i >> 5, d = i & 31;
        float acc = 0.f;
        #pragma unroll 8
        for (int t = 0; t < 64; t++) acc += sc[s][t]*v[t][d];
        attn_out[((size_t)(s*A_ + n))*DIM_ + h*32 + d] = acc;
    }
}

// ---------------- x = LayerNorm(x + add), row width 256, warp per row ----------------
__global__ __launch_bounds__(256)
void add_ln_kernel(float* __restrict__ x, const float* __restrict__ add,
                   const float* __restrict__ g, const float* __restrict__ bta)
{
    int row  = blockIdx.x * 8 + (threadIdx.x >> 5);
    int lane = threadIdx.x & 31;
    float* xr = x + (size_t)row*DIM_;
    const float* ar = add + (size_t)row*DIM_;
    float v[8];
    float s = 0.f;
    #pragma unroll
    for (int i = 0; i < 8; i++) { v[i] = xr[lane + i*32] + ar[lane + i*32]; s += v[i]; }
    #pragma unroll
    for (int o = 16; o; o >>= 1) s += __shfl_xor_sync(~0u, s, o);
    float mean = s * (1.0f/DIM_);
    float var = 0.f;
    #pragma unroll
    for (int i = 0; i < 8; i++) { float d = v[i]-mean; var += d*d; }
    #pragma unroll
    for (int o = 16; o; o >>= 1) var += __shfl_xor_sync(~0u, var, o);
    var *= (1.0f/DIM_);
    float inv = rsqrtf(var + 1e-5f);
    #pragma unroll
    for (int i = 0; i < 8; i++) {
        int cidx = lane + i*32;
        xr[cidx] = (v[i]-mean)*inv*g[cidx] + bta[cidx];
    }
}

// ---------------- Set2Set (6 steps) + memory LSTM; one block per graph ----------------
__global__ __launch_bounds__(256)
void set2set_kernel(const float* __restrict__ x,
                    const float* __restrict__ wih, const float* __restrict__ whh,
                    const float* __restrict__ bih, const float* __restrict__ bhh,
                    const float* __restrict__ mwih,
                    const float* __restrict__ mbih, const float* __restrict__ mbhh,
                    float* __restrict__ h1buf, float* __restrict__ out,
                    int h1_off, int c1_off)
{
    int b = blockIdx.x;
    int tid = threadIdx.x;
    int lane = tid & 31, warp = tid >> 5;     // 8 warps
    __shared__ float h[256], c[256], qs[512], att[512], gates[1024];
    __shared__ float redm[8], reds[8];

    h[tid] = 0.f; c[tid] = 0.f; qs[tid] = 0.f; qs[tid+256] = 0.f;
    __syncthreads();

    const float* xb = x + (size_t)b*A_*DIM_;

    for (int step = 0; step < 6; step++) {
        // gates = qs @ wih^T + bih + h @ whh^T + bhh  (1024 gates, warp-cooperative)
        for (int j = warp*128; j < warp*128 + 128; j++) {
            float acc = 0.f;
            const float* w1 = wih + (size_t)j*512;
            for (int kk = lane; kk < 512; kk += 32) acc += qs[kk]*w1[kk];
            const float* w2 = whh + (size_t)j*256;
            for (int kk = lane; kk < 256; kk += 32) acc += h[kk]*w2[kk];
            #pragma unroll
            for (int o = 16; o; o >>= 1) acc += __shfl_xor_sync(~0u, acc, o);
            if (lane == 0) gates[j] = acc + bih[j] + bhh[j];
        }
        __syncthreads();
        float gi = gates[tid], gf = gates[tid+256], gg = gates[tid+512], go = gates[tid+768];
        float cn = sigmoidf_(gf)*c[tid] + sigmoidf_(gi)*tanhf(gg);
        float hn = sigmoidf_(go)*tanhf(cn);
        __syncthreads();
        c[tid] = cn; h[tid] = hn;
        __syncthreads();

        // e[a] = dot(x[b,a,:], h)
        for (int a = warp*64; a < warp*64 + 64; a++) {
            float acc = 0.f;
            const float* xr = xb + (size_t)a*DIM_;
            #pragma unroll
            for (int d = lane; d < 256; d += 32) acc += xr[d]*h[d];
            #pragma unroll
            for (int o = 16; o; o >>= 1) acc += __shfl_xor_sync(~0u, acc, o);
            if (lane == 0) att[a] = acc;
        }
        __syncthreads();

        // softmax over a (512)
        float lm = -1e30f;
        for (int a = tid; a < 512; a += 256) lm = fmaxf(lm, att[a]);
        #pragma unroll
        for (int o = 16; o; o >>= 1) lm = fmaxf(lm, __shfl_xor_sync(~0u, lm, o));
        if (lane == 0) redm[warp] = lm;
        __syncthreads();
        float mx = redm[0];
        #pragma unroll
        for (int w = 1; w < 8; w++) mx = fmaxf(mx, redm[w]);
        float ls = 0.f;
        for (int a = tid; a < 512; a += 256) { float e = expf(att[a]-mx); att[a] = e; ls += e; }
        #pragma unroll
        for (int o = 16; o; o >>= 1) ls += __shfl_xor_sync(~0u, ls, o);
        if (lane == 0) reds[warp] = ls;
        __syncthreads();
        float S = 0.f;
        #pragma unroll
        for (int w = 0; w < 8; w++) S += reds[w];
        float inv = 1.0f / S;

        // r[d] = sum_a att[a]*x[b,a,d]
        float r = 0.f;
        for (int a = 0; a < 512; a++) r += att[a]*xb[(size_t)a*DIM_ + tid];
        r *= inv;
        __syncthreads();
        qs[tid] = h[tid];
        qs[256+tid] = r;
        __syncthreads();
    }

    // memory LSTM single step, zero hx/cx
    for (int j = warp*128; j < warp*128 + 128; j++) {
        float acc = 0.f;
        const float* w1 = mwih + (size_t)j*512;
        for (int kk = lane; kk < 512; kk += 32) acc += qs[kk]*w1[kk];
        #pragma unroll
        for (int o = 16; o; o >>= 1) acc += __shfl_xor_sync(~0u, acc, o);
        if (lane == 0) gates[j] = acc + mbih[j] + mbhh[j];
    }
    __syncthreads();
    float gi = gates[tid], gg = gates[tid+512], go = gates[tid+768];
    float c1 = sigmoidf_(gi)*tanhf(gg);
    float h1 = sigmoidf_(go)*tanhf(c1);
    h1buf[b*DIM_ + tid] = h1;
    out[h1_off + b*DIM_ + tid] = h1;
    out[c1_off + b*DIM_ + tid] = c1;
}

// ---------------- offsets: prefix sum of torsion_list_sizes (int32/int64 autodetect) ----------------
__global__ void offsets_kernel(const int* __restrict__ raw)
{
    if (threadIdx.x == 0 && blockIdx.x == 0) {
        bool is64 = (raw[1] == 0);   // arange: int32 -> raw[1]=1 ; int64 -> raw[1]=0 (hi word)
        g_off[0] = 0;
        for (int b = 0; b < B_; b++) {
            int sz = is64 ? raw[2*b] : raw[b];
            g_off[b+1] = g_off[b] + sz;
        }
    }
}

// ---------------- feat materialization (torch transpose/reshape layout) ----------------
__global__ void feat_kernel(const float* __restrict__ x, const float* __restrict__ h1,
                            const int* __restrict__ nonring, const int* __restrict__ nrbidx,
                            float* __restrict__ feat)
{
    int idx = blockIdx.x * blockDim.x + threadIdx.x;   // T*1280
    if (idx >= T_*5*DIM_) return;
    int d   = idx / (T_*5);
    int rem = idx - d*(T_*5);
    int t   = rem / 5;
    int s   = rem - t*5;
    float v;
    if (s == 0) {
        v = h1[nrbidx[t]*DIM_ + d];
    } else {
        // gathered[j,t] = out_flat[ nonring_flat[j*T + t] ]
        int atom = nonring[(s-1)*T_ + t];
        v = x[(size_t)atom*DIM_ + d];
    }
    feat[idx] = v;
}

// ---------------- lin2: (T,6) = o1 @ w^T + b ----------------
__global__ void lin2_kernel(const float* __restrict__ o1, const float* __restrict__ w,
                            const float* __restrict__ b, float* __restrict__ o2)
{
    int idx = blockIdx.x * blockDim.x + threadIdx.x;   // T*6
    if (idx >= T_*ACT_) return;
    int t = idx / ACT_, n = idx - t*ACT_;
    float acc = b[n];
    const float* orow = o1 + (size_t)t*DIM_;
    const float* wrow = w + (size_t)n*DIM_;
    #pragma unroll 8
    for (int kk = 0; kk < DIM_; kk++) acc += orow[kk]*wrow[kk];
    o2[idx] = acc;
}

// ---------------- zero logit region ----------------
__global__ void zero_kernel(float* __restrict__ out, int n)
{
    int idx = blockIdx.x * blockDim.x + threadIdx.x;
    if (idx < n) out[idx] = 0.0f;
}

// ---------------- scatter o2 -> padded logit ----------------
__global__ void scatter_kernel(const float* __restrict__ o2, float* __restrict__ out, int max_s)
{
    int t = blockIdx.x * blockDim.x + threadIdx.x;
    if (t >= T_) return;
    int lo = 0, hi = B_-1;
    while (lo < hi) {
        int mid = (lo + hi + 1) >> 1;
        if (g_off[mid] <= t) lo = mid; else hi = mid - 1;
    }
    int b = lo;
    int pos = t - g_off[b];
    #pragma unroll
    for (int n = 0; n < ACT_; n++)
        out[((size_t)(b*max_s + pos))*ACT_ + n] = o2[t*ACT_ + n];
}

// ---------------- host launch ----------------
extern "C" void kernel_launch(void* const* d_in, const int* in_sizes, int n_in,
                              void* d_out, int out_size)
{
    const float* data     = (const float*)d_in[0];
    const int*   nonring  = (const int*)  d_in[1];
    const int*   nrbidx   = (const int*)  d_in[2];
    const int*   sizes_raw= (const int*)  d_in[3];
    const float* lin0_w   = (const float*)d_in[4];
    const float* lin0_b   = (const float*)d_in[5];
    const float* qkv_w    = (const float*)d_in[6];
    const float* qkv_b    = (const float*)d_in[7];
    const float* out_w    = (const float*)d_in[8];
    const float* out_b    = (const float*)d_in[9];
    const float* ff1_w    = (const float*)d_in[10];
    const float* ff1_b    = (const float*)d_in[11];
    const float* ff2_w    = (const float*)d_in[12];
    const float* ff2_b    = (const float*)d_in[13];
    const float* ln1_g    = (const float*)d_in[14];
    const float* ln1_b    = (const float*)d_in[15];
    const float* ln2_g    = (const float*)d_in[16];
    const float* ln2_b    = (const float*)d_in[17];
    const float* s2s_wih  = (const float*)d_in[18];
    const float* s2s_whh  = (const float*)d_in[19];
    const float* s2s_bih  = (const float*)d_in[20];
    const float* s2s_bhh  = (const float*)d_in[21];
    const float* mem_wih  = (const float*)d_in[22];
    const float* mem_bih  = (const float*)d_in[24];
    const float* mem_bhh  = (const float*)d_in[25];
    const float* lin1_w   = (const float*)d_in[26];
    const float* lin1_b   = (const float*)d_in[27];
    const float* lin2_w   = (const float*)d_in[28];
    const float* lin2_b   = (const float*)d_in[29];

    float* out = (float*)d_out;
    int logit_elems = out_size - 2*B_*DIM_;
    int max_s = logit_elems / (B_*ACT_);

    float *px, *pqkv, *pattn, *ptmp, *pff, *ph1, *pfeat, *po1, *po2;
    cudaGetSymbolAddress((void**)&px,   g_x);
    cudaGetSymbolAddress((void**)&pqkv, g_qkv);
    cudaGetSymbolAddress((void**)&pattn,g_attn);
    cudaGetSymbolAddress((void**)&ptmp, g_tmp);
    cudaGetSymbolAddress((void**)&pff,  g_ff);
    cudaGetSymbolAddress((void**)&ph1,  g_h1v);
    cudaGetSymbolAddress((void**)&pfeat,g_feat);
    cudaGetSymbolAddress((void**)&po1,  g_o1);
    cudaGetSymbolAddress((void**)&po2,  g_o2);

    offsets_kernel<<<1, 32>>>(sizes_raw);

    lin0_kernel<<<(M_*DIM_)/256, 256>>>(data, lin0_w, lin0_b, px);

    for (int l = 0; l < LAYERS_; l++) {
        // QKV: (M,768) = x @ Wqkv^T + b
        {
            dim3 grid(768/64, M_/64);
            sgemm_nt<1,0><<<grid, 256>>>(px, qkv_w + (size_t)l*768*DIM_,
                                         qkv_b + l*768, pqkv, M_, 768, DIM_);
        }
        attn_kernel<<<A_*HEADS_, 128>>>(pqkv, pattn);
        // O-proj
        {
            dim3 grid(DIM_/64, M_/64);
            sgemm_nt<1,0><<<grid, 256>>>(pattn, out_w + (size_t)l*DIM_*DIM_,
                                         out_b + l*DIM_, ptmp, M_, DIM_, DIM_);
        }
        add_ln_kernel<<<M_/8, 256>>>(px, ptmp, ln1_g + l*DIM_, ln1_b + l*DIM_);
        // FF1 (relu)
        {
            dim3 grid(FF_/64, M_/64);
            sgemm_nt<1,1><<<grid, 256>>>(px, ff1_w + (size_t)l*FF_*DIM_,
                                         ff1_b + l*FF_, pff, M_, FF_, DIM_);
        }
        // FF2
        {
            dim3 grid(DIM_/64, M_/64);
            sgemm_nt<1,0><<<grid, 256>>>(pff, ff2_w + (size_t)l*DIM_*FF_,
                                         ff2_b + l*DIM_, ptmp, M_, DIM_, FF_);
        }
        add_ln_kernel<<<M_/8, 256>>>(px, ptmp, ln2_g + l*DIM_, ln2_b + l*DIM_);
    }

    set2set_kernel<<<B_, 256>>>(px, s2s_wih, s2s_whh, s2s_bih, s2s_bhh,
                                mem_wih, mem_bih, mem_bhh,
                                ph1, out, logit_elems, logit_elems + B_*DIM_);

    feat_kernel<<<(T_*5*DIM_ + 255)/256, 256>>>(px, ph1, nonring, nrbidx, pfeat);

    {
        dim3 grid(DIM_/64, (T_ + 63)/64);
        sgemm_nt<1,1><<<grid, 256>>>(pfeat, lin1_w, lin1_b, po1, T_, DIM_, 5*DIM_);
    }
    lin2_kernel<<<(T_*ACT_ + 255)/256, 256>>>(po1, lin2_w, lin2_b, po2);

    zero_kernel<<<(logit_elems + 255)/256, 256>>>(out, logit_elems);
    scatter_kernel<<<(T_ + 255)/256, 256>>>(po2, out, max_s);
}

// round 2
// speedup vs baseline: 1.0005x; 1.0005x over previous
#include <cuda_runtime.h>
#include <math.h>

#define B_     64
#define A_     512
#define DIM_   256
#define M_     (B_*A_)     // 32768
#define HEADS_ 8
#define DH_    32
#define LAYERS_ 6
#define FF_    2048
#define T_     2016
#define ACT_   6

// ---------------- scratch (static device globals; no allocation) ----------------
__device__ float g_x   [(size_t)M_*DIM_];
__device__ float g_qkv [(size_t)M_*3*DIM_];
__device__ float g_attn[(size_t)M_*DIM_];
__device__ float g_tmp [(size_t)M_*DIM_];
__device__ float g_ff  [(size_t)M_*FF_];
__device__ float g_h1v [B_*DIM_];
__device__ float g_feat[(size_t)T_*5*DIM_];
__device__ float g_o1  [(size_t)T_*DIM_];
__device__ float g_o2  [T_*ACT_];
__device__ int   g_off [B_+1];

__device__ __forceinline__ float sigmoidf_(float x) { return 1.0f / (1.0f + expf(-x)); }

// ---------------- lin0: x = relu(data @ W^T + b), data (M,3) ----------------
__global__ void lin0_kernel(const float* __restrict__ data,
                            const float* __restrict__ w,   // (256,3)
                            const float* __restrict__ b,
                            float* __restrict__ x)
{
    int idx = blockIdx.x * blockDim.x + threadIdx.x;   // M*256 threads
    if (idx >= M_*DIM_) return;
    int m = idx >> 8;
    int n = idx & 255;
    float d0 = data[m*3+0], d1 = data[m*3+1], d2 = data[m*3+2];
    float v = d0*w[n*3+0] + d1*w[n*3+1] + d2*w[n*3+2] + b[n];
    x[idx] = fmaxf(v, 0.0f);
}

// ---------------- generic SGEMM, C[m,n] = act(sum_k A[m,k]*B[n,k] + bias[n]) ----------------
// A: (M,K) row-major; B: (N,K) row-major (i.e. C = A @ B^T). K % 16 == 0.
template<int BIAS, int RELU>
__global__ __launch_bounds__(256)
void sgemm_nt(const float* __restrict__ A, const float* __restrict__ Bm,
              const float* __restrict__ bias, float* __restrict__ C,
              int M, int N, int K)
{
    __shared__ float As[16][64];
    __shared__ float Bs[16][64];
    const int tid = threadIdx.x;
    const int bm = blockIdx.y * 64;
    const int bn = blockIdx.x * 64;
    const int ty = tid >> 4, tx = tid & 15;
    const int lr = tid >> 2;            // 0..63
    const int lk = (tid & 3) << 2;      // 0,4,8,12
    float acc[4][4] = {};

    for (int k0 = 0; k0 < K; k0 += 16) {
        float4 av = make_float4(0.f,0.f,0.f,0.f);
        float4 bv = make_float4(0.f,0.f,0.f,0.f);
        int ar = bm + lr;
        if (ar < M) av = *reinterpret_cast<const float4*>(A  + (size_t)ar*K + k0 + lk);
        int br = bn + lr;
        if (br < N) bv = *reinterpret_cast<const float4*>(Bm + (size_t)br*K + k0 + lk);
        As[lk+0][lr]=av.x; As[lk+1][lr]=av.y; As[lk+2][lr]=av.z; As[lk+3][lr]=av.w;
        Bs[lk+0][lr]=bv.x; Bs[lk+1][lr]=bv.y; Bs[lk+2][lr]=bv.z; Bs[lk+3][lr]=bv.w;
        __syncthreads();
        #pragma unroll
        for (int k = 0; k < 16; k++) {
            float4 a4 = *reinterpret_cast<float4*>(&As[k][ty*4]);
            float4 b4 = *reinterpret_cast<float4*>(&Bs[k][tx*4]);
            float a[4] = {a4.x, a4.y, a4.z, a4.w};
            float bb[4] = {b4.x, b4.y, b4.z, b4.w};
            #pragma unroll
            for (int i = 0; i < 4; i++)
                #pragma unroll
                for (int j = 0; j < 4; j++)
                    acc[i][j] += a[i]*bb[j];
        }
        __syncthreads();
    }

    #pragma unroll
    for (int i = 0; i < 4; i++) {
        int m = bm + ty*4 + i;
        if (m >= M) continue;
        #pragma unroll
        for (int j = 0; j < 4; j++) {
            int n = bn + tx*4 + j;
            if (n >= N) continue;
            float v = acc[i][j];
            if (BIAS) v += bias[n];
            if (RELU) v = fmaxf(v, 0.0f);
            C[(size_t)m*N + n] = v;
        }
    }
}

// ---------------- attention over the batch axis: one block per (atom n, head h) ----------------
__global__ __launch_bounds__(128)
void attn_kernel(const float* __restrict__ qkv, float* __restrict__ attn_out)
{
    int nh = blockIdx.x;
    int n = nh >> 3;
    int h = nh & 7;
    __shared__ float q[64][32], k[64][32], v[64][32];
    __shared__ float sc[64][65];
    int tid = threadIdx.x;

    for (int i = tid; i < 64*32; i += 128) {
        int s = i >> 5, d = i & 31;
        size_t base = ((size_t)(s*A_ + n))*768 + h*32 + d;
        q[s][d] = qkv[base];
        k[s][d] = qkv[base + 256];
        v[s][d] = qkv[base + 512];
    }
    __syncthreads();

    const float scale = 0.17677669529663687f;  // 1/sqrt(32)
    for (int i = tid; i < 64*64; i += 128) {
        int s = i >> 6, t = i & 63;
        float acc = 0.f;
        #pragma unroll 8
        for (int d = 0; d < 32; d++) acc += q[s][d]*k[t][d];
        sc[s][t] = acc * scale;
    }
    __syncthreads();

    if (tid < 64) {
        float mx = -1e30f;
        for (int t = 0; t < 64; t++) mx = fmaxf(mx, sc[tid][t]);
        float sum = 0.f;
        for (int t = 0; t < 64; t++) { float e = expf(sc[tid][t]-mx); sc[tid][t]=e; sum+=e; }
        float inv = 1.0f / sum;
        for (int t = 0; t < 64; t++) sc[tid][t] *= inv;
    }
    __syncthreads();

    for (int i = tid; i < 64*32; i += 128) {
        int s = i >> 5, d = i & 31;
        float acc = 0.f;
        #pragma unroll 8
        for (int t = 0; t < 64; t++) acc += sc[s][t]*v[t][d];
        attn_out[((size_t)(s*A_ + n))*DIM_ + h*32 + d] = acc;
    }
}

// ---------------- x = LayerNorm(x + add), row width 256, warp per row ----------------
__global__ __launch_bounds__(256)
void add_ln_kernel(float* __restrict__ x, const float* __restrict__ add,
                   const float* __restrict__ g, const float* __restrict__ bta)
{
    int row  = blockIdx.x * 8 + (threadIdx.x >> 5);
    int lane = threadIdx.x & 31;
    float* xr = x + (size_t)row*DIM_;
    const float* ar = add + (size_t)row*DIM_;
    float v[8];
    float s = 0.f;
    #pragma unroll
    for (int i = 0; i < 8; i++) { v[i] = xr[lane + i*32] + ar[lane + i*32]; s += v[i]; }
    #pragma unroll
    for (int o = 16; o; o >>= 1) s += __shfl_xor_sync(~0u, s, o);
    float mean = s * (1.0f/DIM_);
    float var = 0.f;
    #pragma unroll
    for (int i = 0; i < 8; i++) { float d = v[i]-mean; var += d*d; }
    #pragma unroll
    for (int o = 16; o; o >>= 1) var += __shfl_xor_sync(~0u, var, o);
    var *= (1.0f/DIM_);
    float inv = rsqrtf(var + 1e-5f);
    #pragma unroll
    for (int i = 0; i < 8; i++) {
        int cidx = lane + i*32;
        xr[cidx] = (v[i]-mean)*inv*g[cidx] + bta[cidx];
    }
}

// ---------------- Set2Set (6 steps) + memory LSTM; one block per graph ----------------
__global__ __launch_bounds__(256)
void set2set_kernel(const float* __restrict__ x,
                    const float* __restrict__ wih, const float* __restrict__ whh,
                    const float* __restrict__ bih, const float* __restrict__ bhh,
                    const float* __restrict__ mwih,
                    const float* __restrict__ mbih, const float* __restrict__ mbhh,
                    float* __restrict__ h1buf, float* __restrict__ out,
                    int h1_off, int c1_off)
{
    int b = blockIdx.x;
    int tid = threadIdx.x;
    int lane = tid & 31, warp = tid >> 5;     // 8 warps
    __shared__ float h[256], c[256], qs[512], att[512], gates[1024];
    __shared__ float redm[8], reds[8];

    h[tid] = 0.f; c[tid] = 0.f; qs[tid] = 0.f; qs[tid+256] = 0.f;
    __syncthreads();

    const float* xb = x + (size_t)b*A_*DIM_;

    for (int step = 0; step < 6; step++) {
        // gates = qs @ wih^T + bih + h @ whh^T + bhh  (1024 gates, warp-cooperative)
        for (int j = warp*128; j < warp*128 + 128; j++) {
            float acc = 0.f;
            const float* w1 = wih + (size_t)j*512;
            for (int kk = lane; kk < 512; kk += 32) acc += qs[kk]*w1[kk];
            const float* w2 = whh + (size_t)j*256;
            for (int kk = lane; kk < 256; kk += 32) acc += h[kk]*w2[kk];
            #pragma unroll
            for (int o = 16; o; o >>= 1) acc += __shfl_xor_sync(~0u, acc, o);
            if (lane == 0) gates[j] = acc + bih[j] + bhh[j];
        }
        __syncthreads();
        float gi = gates[tid], gf = gates[tid+256], gg = gates[tid+512], go = gates[tid+768];
        float cn = sigmoidf_(gf)*c[tid] + sigmoidf_(gi)*tanhf(gg);
        float hn = sigmoidf_(go)*tanhf(cn);
        __syncthreads();
        c[tid] = cn; h[tid] = hn;
        __syncthreads();

        // e[a] = dot(x[b,a,:], h)
        for (int a = warp*64; a < warp*64 + 64; a++) {
            float acc = 0.f;
            const float* xr = xb + (size_t)a*DIM_;
            #pragma unroll
            for (int d = lane; d < 256; d += 32) acc += xr[d]*h[d];
            #pragma unroll
            for (int o = 16; o; o >>= 1) acc += __shfl_xor_sync(~0u, acc, o);
            if (lane == 0) att[a] = acc;
        }
        __syncthreads();

        // softmax over a (512)
        float lm = -1e30f;
        for (int a = tid; a < 512; a += 256) lm = fmaxf(lm, att[a]);
        #pragma unroll
        for (int o = 16; o; o >>= 1) lm = fmaxf(lm, __shfl_xor_sync(~0u, lm, o));
        if (lane == 0) redm[warp] = lm;
        __syncthreads();
        float mx = redm[0];
        #pragma unroll
        for (int w = 1; w < 8; w++) mx = fmaxf(mx, redm[w]);
        float ls = 0.f;
        for (int a = tid; a < 512; a += 256) { float e = expf(att[a]-mx); att[a] = e; ls += e; }
        #pragma unroll
        for (int o = 16; o; o >>= 1) ls += __shfl_xor_sync(~0u, ls, o);
        if (lane == 0) reds[warp] = ls;
        __syncthreads();
        float S = 0.f;
        #pragma unroll
        for (int w = 0; w < 8; w++) S += reds[w];
        float inv = 1.0f / S;

        // r[d] = sum_a att[a]*x[b,a,d]
        float r = 0.f;
        for (int a = 0; a < 512; a++) r += att[a]*xb[(size_t)a*DIM_ + tid];
        r *= inv;
        __syncthreads();
        qs[tid] = h[tid];
        qs[256+tid] = r;
        __syncthreads();
    }

    // memory LSTM single step, zero hx/cx
    for (int j = warp*128; j < warp*128 + 128; j++) {
        float acc = 0.f;
        const float* w1 = mwih + (size_t)j*512;
        for (int kk = lane; kk < 512; kk += 32) acc += qs[kk]*w1[kk];
        #pragma unroll
        for (int o = 16; o; o >>= 1) acc += __shfl_xor_sync(~0u, acc, o);
        if (lane == 0) gates[j] = acc + mbih[j] + mbhh[j];
    }
    __syncthreads();
    float gi = gates[tid], gg = gates[tid+512], go = gates[tid+768];
    float c1 = sigmoidf_(gi)*tanhf(gg);
    float h1 = sigmoidf_(go)*tanhf(c1);
    h1buf[b*DIM_ + tid] = h1;
    out[h1_off + b*DIM_ + tid] = h1;
    out[c1_off + b*DIM_ + tid] = c1;
}

// ---------------- offsets: prefix sum of torsion_list_sizes (int32/int64 autodetect) ----------------
__global__ void offsets_kernel(const int* __restrict__ raw)
{
    if (threadIdx.x == 0 && blockIdx.x == 0) {
        bool is64 = (raw[1] == 0);   // arange: int32 -> raw[1]=1 ; int64 -> raw[1]=0 (hi word)
        g_off[0] = 0;
        for (int b = 0; b < B_; b++) {
            int sz = is64 ? raw[2*b] : raw[b];
            g_off[b+1] = g_off[b] + sz;
        }
    }
}

// ---------------- feat materialization (torch transpose/reshape layout) ----------------
__global__ void feat_kernel(const float* __restrict__ x, const float* __restrict__ h1,
                            const int* __restrict__ nonring, const int* __restrict__ nrbidx,
                            float* __restrict__ feat)
{
    int idx = blockIdx.x * blockDim.x + threadIdx.x;   // T*1280
    if (idx >= T_*5*DIM_) return;
    int d   = idx / (T_*5);
    int rem = idx - d*(T_*5);
    int t   = rem / 5;
    int s   = rem - t*5;
    float v;
    if (s == 0) {
        v = h1[nrbidx[t]*DIM_ + d];
    } else {
        // gathered[j,t] = out_flat[ nonring_flat[j*T + t] ]
        int atom = nonring[(s-1)*T_ + t];
        v = x[(size_t)atom*DIM_ + d];
    }
    feat[idx] = v;
}

// ---------------- lin2: (T,6) = o1 @ w^T + b ----------------
__global__ void lin2_kernel(const float* __restrict__ o1, const float* __restrict__ w,
                            const float* __restrict__ b, float* __restrict__ o2)
{
    int idx = blockIdx.x * blockDim.x + threadIdx.x;   // T*6
    if (idx >= T_*ACT_) return;
    int t = idx / ACT_, n = idx - t*ACT_;
    float acc = b[n];
    const float* orow = o1 + (size_t)t*DIM_;
    const float* wrow = w + (size_t)n*DIM_;
    #pragma unroll 8
    for (int kk = 0; kk < DIM_; kk++) acc += orow[kk]*wrow[kk];
    o2[idx] = acc;
}

// ---------------- zero logit region ----------------
__global__ void zero_kernel(float* __restrict__ out, int n)
{
    int idx = blockIdx.x * blockDim.x + threadIdx.x;
    if (idx < n) out[idx] = 0.0f;
}

// ---------------- scatter o2 -> padded logit ----------------
__global__ void scatter_kernel(const float* __restrict__ o2, float* __restrict__ out, int max_s)
{
    int t = blockIdx.x * blockDim.x + threadIdx.x;
    if (t >= T_) return;
    int lo = 0, hi = B_-1;
    while (lo < hi) {
        int mid = (lo + hi + 1) >> 1;
        if (g_off[mid] <= t) lo = mid; else hi = mid - 1;
    }
    int b = lo;
    int pos = t - g_off[b];
    #pragma unroll
    for (int n = 0; n < ACT_; n++)
        out[((size_t)(b*max_s + pos))*ACT_ + n] = o2[t*ACT_ + n];
}

// ---------------- host launch ----------------
extern "C" void kernel_launch(void* const* d_in, const int* in_sizes, int n_in,
                              void* d_out, int out_size)
{
    const float* data     = (const float*)d_in[0];
    const int*   nonring  = (const int*)  d_in[1];
    const int*   nrbidx   = (const int*)  d_in[2];
    const int*   sizes_raw= (const int*)  d_in[3];
    const float* lin0_w   = (const float*)d_in[4];
    const float* lin0_b   = (const float*)d_in[5];
    const float* qkv_w    = (const float*)d_in[6];
    const float* qkv_b    = (const float*)d_in[7];
    const float* out_w    = (const float*)d_in[8];
    const float* out_b    = (const float*)d_in[9];
    const float* ff1_w    = (const float*)d_in[10];
    const float* ff1_b    = (const float*)d_in[11];
    const float* ff2_w    = (const float*)d_in[12];
    const float* ff2_b    = (const float*)d_in[13];
    const float* ln1_g    = (const float*)d_in[14];
    const float* ln1_b    = (const float*)d_in[15];
    const float* ln2_g    = (const float*)d_in[16];
    const float* ln2_b    = (const float*)d_in[17];
    const float* s2s_wih  = (const float*)d_in[18];
    const float* s2s_whh  = (const float*)d_in[19];
    const float* s2s_bih  = (const float*)d_in[20];
    const float* s2s_bhh  = (const float*)d_in[21];
    const float* mem_wih  = (const float*)d_in[22];
    const float* mem_bih  = (const float*)d_in[24];
    const float* mem_bhh  = (const float*)d_in[25];
    const float* lin1_w   = (const float*)d_in[26];
    const float* lin1_b   = (const float*)d_in[27];
    const float* lin2_w   = (const float*)d_in[28];
    const float* lin2_b   = (const float*)d_in[29];

    float* out = (float*)d_out;
    int logit_elems = out_size - 2*B_*DIM_;
    int max_s = logit_elems / (B_*ACT_);

    float *px, *pqkv, *pattn, *ptmp, *pff, *ph1, *pfeat, *po1, *po2;
    cudaGetSymbolAddress((void**)&px,   g_x);
    cudaGetSymbolAddress((void**)&pqkv, g_qkv);
    cudaGetSymbolAddress((void**)&pattn,g_attn);
    cudaGetSymbolAddress((void**)&ptmp, g_tmp);
    cudaGetSymbolAddress((void**)&pff,  g_ff);
    cudaGetSymbolAddress((void**)&ph1,  g_h1v);
    cudaGetSymbolAddress((void**)&pfeat,g_feat);
    cudaGetSymbolAddress((void**)&po1,  g_o1);
    cudaGetSymbolAddress((void**)&po2,  g_o2);

    offsets_kernel<<<1, 32>>>(sizes_raw);

    lin0_kernel<<<(M_*DIM_)/256, 256>>>(data, lin0_w, lin0_b, px);

    for (int l = 0; l < LAYERS_; l++) {
        // QKV: (M,768) = x @ Wqkv^T + b
        {
            dim3 grid(768/64, M_/64);
            sgemm_nt<1,0><<<grid, 256>>>(px, qkv_w + (size_t)l*768*DIM_,
                                         qkv_b + l*768, pqkv, M_, 768, DIM_);
        }
        attn_kernel<<<A_*HEADS_, 128>>>(pqkv, pattn);
        // O-proj
        {
            dim3 grid(DIM_/64, M_/64);
            sgemm_nt<1,0><<<grid, 256>>>(pattn, out_w + (size_t)l*DIM_*DIM_,
                                         out_b + l*DIM_, ptmp, M_, DIM_, DIM_);
        }
        add_ln_kernel<<<M_/8, 256>>>(px, ptmp, ln1_g + l*DIM_, ln1_b + l*DIM_);
        // FF1 (relu)
        {
            dim3 grid(FF_/64, M_/64);
            sgemm_nt<1,1><<<grid, 256>>>(px, ff1_w + (size_t)l*FF_*DIM_,
                                         ff1_b + l*FF_, pff, M_, FF_, DIM_);
        }
        // FF2
        {
            dim3 grid(DIM_/64, M_/64);
            sgemm_nt<1,0><<<grid, 256>>>(pff, ff2_w + (size_t)l*DIM_*FF_,
                                         ff2_b + l*DIM_, ptmp, M_, DIM_, FF_);
        }
        add_ln_kernel<<<M_/8, 256>>>(px, ptmp, ln2_g + l*DIM_, ln2_b + l*DIM_);
    }

    set2set_kernel<<<B_, 256>>>(px, s2s_wih, s2s_whh, s2s_bih, s2s_bhh,
                                mem_wih, mem_bih, mem_bhh,
                                ph1, out, logit_elems, logit_elems + B_*DIM_);

    feat_kernel<<<(T_*5*DIM_ + 255)/256, 256>>>(px, ph1, nonring, nrbidx, pfeat);

    {
        dim3 grid(DIM_/64, (T_ + 63)/64);
        sgemm_nt<1,1><<<grid, 256>>>(pfeat, lin1_w, lin1_b, po1, T_, DIM_, 5*DIM_);
    }
    lin2_kernel<<<(T_*ACT_ + 255)/256, 256>>>(po1, lin2_w, lin2_b, po2);

    zero_kernel<<<(logit_elems + 255)/256, 256>>>(out, logit_elems);
    scatter_kernel<<<(T_ + 255)/256, 256>>>(po2, out, max_s);
}

// round 3
// speedup vs baseline: 1.0005x; 1.0000x over previous
#include <cuda_runtime.h>
#include <math.h>

#define B_     64
#define A_     512
#define DIM_   256
#define M_     (B_*A_)     // 32768
#define HEADS_ 8
#define DH_    32
#define LAYERS_ 6
#define FF_    2048
#define T_     2016
#define ACT_   6

// ---------------- scratch (static device globals; no allocation) ----------------
__device__ float g_x   [(size_t)M_*DIM_];
__device__ float g_qkv [(size_t)M_*3*DIM_];
__device__ float g_attn[(size_t)M_*DIM_];
__device__ float g_tmp [(size_t)M_*DIM_];
__device__ float g_ff  [(size_t)M_*FF_];
__device__ float g_h1v [B_*DIM_];
__device__ float g_feat[(size_t)T_*5*DIM_];
__device__ float g_o1  [(size_t)T_*DIM_];
__device__ float g_o2  [T_*ACT_];
__device__ int   g_off [B_+1];

__device__ __forceinline__ float sigmoidf_(float x) { return 1.0f / (1.0f + expf(-x)); }

// ---------------- lin0: x = relu(data @ W^T + b), data (M,3) ----------------
__global__ void lin0_kernel(const float* __restrict__ data,
                            const float* __restrict__ w,   // (256,3)
                            const float* __restrict__ b,
                            float* __restrict__ x)
{
    int idx = blockIdx.x * blockDim.x + threadIdx.x;   // M*256 threads
    if (idx >= M_*DIM_) return;
    int m = idx >> 8;
    int n = idx & 255;
    float d0 = data[m*3+0], d1 = data[m*3+1], d2 = data[m*3+2];
    float v = d0*w[n*3+0] + d1*w[n*3+1] + d2*w[n*3+2] + b[n];
    x[idx] = fmaxf(v, 0.0f);
}

// ---------------- generic SGEMM, C[m,n] = act(sum_k A[m,k]*B[n,k] + bias[n]) ----------------
// A: (M,K) row-major; B: (N,K) row-major (i.e. C = A @ B^T). K % 16 == 0.
template<int BIAS, int RELU>
__global__ __launch_bounds__(256)
void sgemm_nt(const float* __restrict__ A, const float* __restrict__ Bm,
              const float* __restrict__ bias, float* __restrict__ C,
              int M, int N, int K)
{
    __shared__ float As[16][64];
    __shared__ float Bs[16][64];
    const int tid = threadIdx.x;
    const int bm = blockIdx.y * 64;
    const int bn = blockIdx.x * 64;
    const int ty = tid >> 4, tx = tid & 15;
    const int lr = tid >> 2;            // 0..63
    const int lk = (tid & 3) << 2;      // 0,4,8,12
    float acc[4][4] = {};

    for (int k0 = 0; k0 < K; k0 += 16) {
        float4 av = make_float4(0.f,0.f,0.f,0.f);
        float4 bv = make_float4(0.f,0.f,0.f,0.f);
        int ar = bm + lr;
        if (ar < M) av = *reinterpret_cast<const float4*>(A  + (size_t)ar*K + k0 + lk);
        int br = bn + lr;
        if (br < N) bv = *reinterpret_cast<const float4*>(Bm + (size_t)br*K + k0 + lk);
        As[lk+0][lr]=av.x; As[lk+1][lr]=av.y; As[lk+2][lr]=av.z; As[lk+3][lr]=av.w;
        Bs[lk+0][lr]=bv.x; Bs[lk+1][lr]=bv.y; Bs[lk+2][lr]=bv.z; Bs[lk+3][lr]=bv.w;
        __syncthreads();
        #pragma unroll
        for (int k = 0; k < 16; k++) {
            float4 a4 = *reinterpret_cast<float4*>(&As[k][ty*4]);
            float4 b4 = *reinterpret_cast<float4*>(&Bs[k][tx*4]);
            float a[4] = {a4.x, a4.y, a4.z, a4.w};
            float bb[4] = {b4.x, b4.y, b4.z, b4.w};
            #pragma unroll
            for (int i = 0; i < 4; i++)
                #pragma unroll
                for (int j = 0; j < 4; j++)
                    acc[i][j] += a[i]*bb[j];
        }
        __syncthreads();
    }

    #pragma unroll
    for (int i = 0; i < 4; i++) {
        int m = bm + ty*4 + i;
        if (m >= M) continue;
        #pragma unroll
        for (int j = 0; j < 4; j++) {
            int n = bn + tx*4 + j;
            if (n >= N) continue;
            float v = acc[i][j];
            if (BIAS) v += bias[n];
            if (RELU) v = fmaxf(v, 0.0f);
            C[(size_t)m*N + n] = v;
        }
    }
}

// ---------------- attention over the batch axis: one block per (atom n, head h) ----------------
__global__ __launch_bounds__(128)
void attn_kernel(const float* __restrict__ qkv, float* __restrict__ attn_out)
{
    int nh = blockIdx.x;
    int n = nh >> 3;
    int h = nh & 7;
    __shared__ float q[64][32], k[64][32], v[64][32];
    __shared__ float sc[64][65];
    int tid = threadIdx.x;

    for (int i = tid; i < 64*32; i += 128) {
        int s = i >> 5, d = i & 31;
        size_t base = ((size_t)(s*A_ + n))*768 + h*32 + d;
        q[s][d] = qkv[base];
        k[s][d] = qkv[base + 256];
        v[s][d] = qkv[base + 512];
    }
    __syncthreads();

    const float scale = 0.17677669529663687f;  // 1/sqrt(32)
    for (int i = tid; i < 64*64; i += 128) {
        int s = i >> 6, t = i & 63;
        float acc = 0.f;
        #pragma unroll 8
        for (int d = 0; d < 32; d++) acc += q[s][d]*k[t][d];
        sc[s][t] = acc * scale;
    }
    __syncthreads();

    if (tid < 64) {
        float mx = -1e30f;
        for (int t = 0; t < 64; t++) mx = fmaxf(mx, sc[tid][t]);
        float sum = 0.f;
        for (int t = 0; t < 64; t++) { float e = expf(sc[tid][t]-mx); sc[tid][t]=e; sum+=e; }
        float inv = 1.0f / sum;
        for (int t = 0; t < 64; t++) sc[tid][t] *= inv;
    }
    __syncthreads();

    for (int i = tid; i < 64*32; i += 128) {
        int s = i >> 5, d = i & 31;
        float acc = 0.f;
        #pragma unroll 8
        for (int t = 0; t < 64; t++) acc += sc[s][t]*v[t][d];
        attn_out[((size_t)(s*A_ + n))*DIM_ + h*32 + d] = acc;
    }
}

// ---------------- x = LayerNorm(x + add), row width 256, warp per row ----------------
__global__ __launch_bounds__(256)
void add_ln_kernel(float* __restrict__ x, const float* __restrict__ add,
                   const float* __restrict__ g, const float* __restrict__ bta)
{
    int row  = blockIdx.x * 8 + (threadIdx.x >> 5);
    int lane = threadIdx.x & 31;
    float* xr = x + (size_t)row*DIM_;
    const float* ar = add + (size_t)row*DIM_;
    float v[8];
    float s = 0.f;
    #pragma unroll
    for (int i = 0; i < 8; i++) { v[i] = xr[lane + i*32] + ar[lane + i*32]; s += v[i]; }
    #pragma unroll
    for (int o = 16; o; o >>= 1) s += __shfl_xor_sync(~0u, s, o);
    float mean = s * (1.0f/DIM_);
    float var = 0.f;
    #pragma unroll
    for (int i = 0; i < 8; i++) { float d = v[i]-mean; var += d*d; }
    #pragma unroll
    for (int o = 16; o; o >>= 1) var += __shfl_xor_sync(~0u, var, o);
    var *= (1.0f/DIM_);
    float inv = rsqrtf(var + 1e-5f);
    #pragma unroll
    for (int i = 0; i < 8; i++) {
        int cidx = lane + i*32;
        xr[cidx] = (v[i]-mean)*inv*g[cidx] + bta[cidx];
    }
}

// ---------------- Set2Set (6 steps) + memory LSTM; one block per graph ----------------
__global__ __launch_bounds__(256)
void set2set_kernel(const float* __restrict__ x,
                    const float* __restrict__ wih, const float* __restrict__ whh,
                    const float* __restrict__ bih, const float* __restrict__ bhh,
                    const float* __restrict__ mwih,
                    const float* __restrict__ mbih, const float* __restrict__ mbhh,
                    float* __restrict__ h1buf, float* __restrict__ out,
                    int h1_off, int c1_off)
{
    int b = blockIdx.x;
    int tid = threadIdx.x;
    int lane = tid & 31, warp = tid >> 5;     // 8 warps
    __shared__ float h[256], c[256], qs[512], att[512], gates[1024];
    __shared__ float redm[8], reds[8];

    h[tid] = 0.f; c[tid] = 0.f; qs[tid] = 0.f; qs[tid+256] = 0.f;
    __syncthreads();

    const float* xb = x + (size_t)b*A_*DIM_;

    for (int step = 0; step < 6; step++) {
        // gates = qs @ wih^T + bih + h @ whh^T + bhh  (1024 gates, warp-cooperative)
        for (int j = warp*128; j < warp*128 + 128; j++) {
            float acc = 0.f;
            const float* w1 = wih + (size_t)j*512;
            for (int kk = lane; kk < 512; kk += 32) acc += qs[kk]*w1[kk];
            const float* w2 = whh + (size_t)j*256;
            for (int kk = lane; kk < 256; kk += 32) acc += h[kk]*w2[kk];
            #pragma unroll
            for (int o = 16; o; o >>= 1) acc += __shfl_xor_sync(~0u, acc, o);
            if (lane == 0) gates[j] = acc + bih[j] + bhh[j];
        }
        __syncthreads();
        float gi = gates[tid], gf = gates[tid+256], gg = gates[tid+512], go = gates[tid+768];
        float cn = sigmoidf_(gf)*c[tid] + sigmoidf_(gi)*tanhf(gg);
        float hn = sigmoidf_(go)*tanhf(cn);
        __syncthreads();
        c[tid] = cn; h[tid] = hn;
        __syncthreads();

        // e[a] = dot(x[b,a,:], h)
        for (int a = warp*64; a < warp*64 + 64; a++) {
            float acc = 0.f;
            const float* xr = xb + (size_t)a*DIM_;
            #pragma unroll
            for (int d = lane; d < 256; d += 32) acc += xr[d]*h[d];
            #pragma unroll
            for (int o = 16; o; o >>= 1) acc += __shfl_xor_sync(~0u, acc, o);
            if (lane == 0) att[a] = acc;
        }
        __syncthreads();

        // softmax over a (512)
        float lm = -1e30f;
        for (int a = tid; a < 512; a += 256) lm = fmaxf(lm, att[a]);
        #pragma unroll
        for (int o = 16; o; o >>= 1) lm = fmaxf(lm, __shfl_xor_sync(~0u, lm, o));
        if (lane == 0) redm[warp] = lm;
        __syncthreads();
        float mx = redm[0];
        #pragma unroll
        for (int w = 1; w < 8; w++) mx = fmaxf(mx, redm[w]);
        float ls = 0.f;
        for (int a = tid; a < 512; a += 256) { float e = expf(att[a]-mx); att[a] = e; ls += e; }
        #pragma unroll
        for (int o = 16; o; o >>= 1) ls += __shfl_xor_sync(~0u, ls, o);
        if (lane == 0) reds[warp] = ls;
        __syncthreads();
        float S = 0.f;
        #pragma unroll
        for (int w = 0; w < 8; w++) S += reds[w];
        float inv = 1.0f / S;

        // r[d] = sum_a att[a]*x[b,a,d]
        float r = 0.f;
        for (int a = 0; a < 512; a++) r += att[a]*xb[(size_t)a*DIM_ + tid];
        r *= inv;
        __syncthreads();
        qs[tid] = h[tid];
        qs[256+tid] = r;
        __syncthreads();
    }

    // memory LSTM single step, zero hx/cx
    for (int j = warp*128; j < warp*128 + 128; j++) {
        float acc = 0.f;
        const float* w1 = mwih + (size_t)j*512;
        for (int kk = lane; kk < 512; kk += 32) acc += qs[kk]*w1[kk];
        #pragma unroll
        for (int o = 16; o; o >>= 1) acc += __shfl_xor_sync(~0u, acc, o);
        if (lane == 0) gates[j] = acc + mbih[j] + mbhh[j];
    }
    __syncthreads();
    float gi = gates[tid], gg = gates[tid+512], go = gates[tid+768];
    float c1 = sigmoidf_(gi)*tanhf(gg);
    float h1 = sigmoidf_(go)*tanhf(c1);
    h1buf[b*DIM_ + tid] = h1;
    out[h1_off + b*DIM_ + tid] = h1;
    out[c1_off + b*DIM_ + tid] = c1;
}

// ---------------- offsets: prefix sum of torsion_list_sizes (int32/int64 autodetect) ----------------
__global__ void offsets_kernel(const int* __restrict__ raw)
{
    if (threadIdx.x == 0 && blockIdx.x == 0) {
        bool is64 = (raw[1] == 0);   // arange: int32 -> raw[1]=1 ; int64 -> raw[1]=0 (hi word)
        g_off[0] = 0;
        for (int b = 0; b < B_; b++) {
            int sz = is64 ? raw[2*b] : raw[b];
            g_off[b+1] = g_off[b] + sz;
        }
    }
}

// ---------------- feat materialization (torch transpose/reshape layout) ----------------
__global__ void feat_kernel(const float* __restrict__ x, const float* __restrict__ h1,
                            const int* __restrict__ nonring, const int* __restrict__ nrbidx,
                            float* __restrict__ feat)
{
    int idx = blockIdx.x * blockDim.x + threadIdx.x;   // T*1280
    if (idx >= T_*5*DIM_) return;
    int d   = idx / (T_*5);
    int rem = idx - d*(T_*5);
    int t   = rem / 5;
    int s   = rem - t*5;
    float v;
    if (s == 0) {
        v = h1[nrbidx[t]*DIM_ + d];
    } else {
        // gathered[j,t] = out_flat[ nonring_flat[j*T + t] ]
        int atom = nonring[(s-1)*T_ + t];
        v = x[(size_t)atom*DIM_ + d];
    }
    feat[idx] = v;
}

// ---------------- lin2: (T,6) = o1 @ w^T + b ----------------
__global__ void lin2_kernel(const float* __restrict__ o1, const float* __restrict__ w,
                            const float* __restrict__ b, float* __restrict__ o2)
{
    int idx = blockIdx.x * blockDim.x + threadIdx.x;   // T*6
    if (idx >= T_*ACT_) return;
    int t = idx / ACT_, n = idx - t*ACT_;
    float acc = b[n];
    const float* orow = o1 + (size_t)t*DIM_;
    const float* wrow = w + (size_t)n*DIM_;
    #pragma unroll 8
    for (int kk = 0; kk < DIM_; kk++) acc += orow[kk]*wrow[kk];
    o2[idx] = acc;
}

// ---------------- zero logit region ----------------
__global__ void zero_kernel(float* __restrict__ out, int n)
{
    int idx = blockIdx.x * blockDim.x + threadIdx.x;
    if (idx < n) out[idx] = 0.0f;
}

// ---------------- scatter o2 -> padded logit ----------------
__global__ void scatter_kernel(const float* __restrict__ o2, float* __restrict__ out, int max_s)
{
    int t = blockIdx.x * blockDim.x + threadIdx.x;
    if (t >= T_) return;
    int lo = 0, hi = B_-1;
    while (lo < hi) {
        int mid = (lo + hi + 1) >> 1;
        if (g_off[mid] <= t) lo = mid; else hi = mid - 1;
    }
    int b = lo;
    int pos = t - g_off[b];
    #pragma unroll
    for (int n = 0; n < ACT_; n++)
        out[((size_t)(b*max_s + pos))*ACT_ + n] = o2[t*ACT_ + n];
}

// ---------------- host launch ----------------
extern "C" void kernel_launch(void* const* d_in, const int* in_sizes, int n_in,
                              void* d_out, int out_size)
{
    const float* data     = (const float*)d_in[0];
    const int*   nonring  = (const int*)  d_in[1];
    const int*   nrbidx   = (const int*)  d_in[2];
    const int*   sizes_raw= (const int*)  d_in[3];
    const float* lin0_w   = (const float*)d_in[4];
    const float* lin0_b   = (const float*)d_in[5];
    const float* qkv_w    = (const float*)d_in[6];
    const float* qkv_b    = (const float*)d_in[7];
    const float* out_w    = (const float*)d_in[8];
    const float* out_b    = (const float*)d_in[9];
    const float* ff1_w    = (const float*)d_in[10];
    const float* ff1_b    = (const float*)d_in[11];
    const float* ff2_w    = (const float*)d_in[12];
    const float* ff2_b    = (const float*)d_in[13];
    const float* ln1_g    = (const float*)d_in[14];
    const float* ln1_b    = (const float*)d_in[15];
    const float* ln2_g    = (const float*)d_in[16];
    const float* ln2_b    = (const float*)d_in[17];
    const float* s2s_wih  = (const float*)d_in[18];
    const float* s2s_whh  = (const float*)d_in[19];
    const float* s2s_bih  = (const float*)d_in[20];
    const float* s2s_bhh  = (const float*)d_in[21];
    const float* mem_wih  = (const float*)d_in[22];
    const float* mem_bih  = (const float*)d_in[24];
    const float* mem_bhh  = (const float*)d_in[25];
    const float* lin1_w   = (const float*)d_in[26];
    const float* lin1_b   = (const float*)d_in[27];
    const float* lin2_w   = (const float*)d_in[28];
    const float* lin2_b   = (const float*)d_in[29];

    float* out = (float*)d_out;
    int logit_elems = out_size - 2*B_*DIM_;
    int max_s = logit_elems / (B_*ACT_);

    float *px, *pqkv, *pattn, *ptmp, *pff, *ph1, *pfeat, *po1, *po2;
    cudaGetSymbolAddress((void**)&px,   g_x);
    cudaGetSymbolAddress((void**)&pqkv, g_qkv);
    cudaGetSymbolAddress((void**)&pattn,g_attn);
    cudaGetSymbolAddress((void**)&ptmp, g_tmp);
    cudaGetSymbolAddress((void**)&pff,  g_ff);
    cudaGetSymbolAddress((void**)&ph1,  g_h1v);
    cudaGetSymbolAddress((void**)&pfeat,g_feat);
    cudaGetSymbolAddress((void**)&po1,  g_o1);
    cudaGetSymbolAddress((void**)&po2,  g_o2);

    offsets_kernel<<<1, 32>>>(sizes_raw);

    lin0_kernel<<<(M_*DIM_)/256, 256>>>(data, lin0_w, lin0_b, px);

    for (int l = 0; l < LAYERS_; l++) {
        // QKV: (M,768) = x @ Wqkv^T + b
        {
            dim3 grid(768/64, M_/64);
            sgemm_nt<1,0><<<grid, 256>>>(px, qkv_w + (size_t)l*768*DIM_,
                                         qkv_b + l*768, pqkv, M_, 768, DIM_);
        }
        attn_kernel<<<A_*HEADS_, 128>>>(pqkv, pattn);
        // O-proj
        {
            dim3 grid(DIM_/64, M_/64);
            sgemm_nt<1,0><<<grid, 256>>>(pattn, out_w + (size_t)l*DIM_*DIM_,
                                         out_b + l*DIM_, ptmp, M_, DIM_, DIM_);
        }
        add_ln_kernel<<<M_/8, 256>>>(px, ptmp, ln1_g + l*DIM_, ln1_b + l*DIM_);
        // FF1 (relu)
        {
            dim3 grid(FF_/64, M_/64);
            sgemm_nt<1,1><<<grid, 256>>>(px, ff1_w + (size_t)l*FF_*DIM_,
                                         ff1_b + l*FF_, pff, M_, FF_, DIM_);
        }
        // FF2
        {
            dim3 grid(DIM_/64, M_/64);
            sgemm_nt<1,0><<<grid, 256>>>(pff, ff2_w + (size_t)l*DIM_*FF_,
                                         ff2_b + l*DIM_, ptmp, M_, DIM_, FF_);
        }
        add_ln_kernel<<<M_/8, 256>>>(px, ptmp, ln2_g + l*DIM_, ln2_b + l*DIM_);
    }

    set2set_kernel<<<B_, 256>>>(px, s2s_wih, s2s_whh, s2s_bih, s2s_bhh,
                                mem_wih, mem_bih, mem_bhh,
                                ph1, out, logit_elems, logit_elems + B_*DIM_);

    feat_kernel<<<(T_*5*DIM_ + 255)/256, 256>>>(px, ph1, nonring, nrbidx, pfeat);

    {
        dim3 grid(DIM_/64, (T_ + 63)/64);
        sgemm_nt<1,1><<<grid, 256>>>(pfeat, lin1_w, lin1_b, po1, T_, DIM_, 5*DIM_);
    }
    lin2_kernel<<<(T_*ACT_ + 255)/256, 256>>>(po1, lin2_w, lin2_b, po2);

    zero_kernel<<<(logit_elems + 255)/256, 256>>>(out, logit_elems);
    scatter_kernel<<<(T_ + 255)/256, 256>>>(po2, out, max_s);
}